// round 2
// baseline (speedup 1.0000x reference)
#include <cuda_runtime.h>
#include <cstdio>

#define BATCH 4
#define SLEN  2048
#define DMODEL 1024

// Scratch (device globals — no runtime allocation allowed)
__device__ float g_Q[BATCH * SLEN * DMODEL];
__device__ float g_K[BATCH * SLEN * DMODEL];
__device__ float g_V[BATCH * SLEN * DMODEL];
__device__ float g_S[(size_t)BATCH * SLEN * SLEN];

// ---------------------------------------------------------------------------
// Tiled SGEMM: C[M,N] = alpha * A[M,K] @ op(B)
//   TRANSB == 0 : B is [K,N] row-major  (NN)
//   TRANSB == 1 : B is [N,K] row-major, used transposed (NT)
// Tile: 128x128x8, 256 threads, 8x8 micro-tile per thread.
// Requires M,N % 128 == 0 and K % 8 == 0 (true for all calls here).
// blockIdx.z indexes batch via byte strides sA/sB/sC (element strides).
// ---------------------------------------------------------------------------
template <int TRANSB>
__global__ __launch_bounds__(256) void gemm128(
    const float* __restrict__ A, const float* __restrict__ B,
    float* __restrict__ C, int M, int N, int K,
    size_t sA, size_t sB, size_t sC, float alpha)
{
    A += (size_t)blockIdx.z * sA;
    B += (size_t)blockIdx.z * sB;
    C += (size_t)blockIdx.z * sC;

    __shared__ float As[8][132];
    __shared__ float Bs[8][132];

    const int tid = threadIdx.x;
    const int tx = tid & 15;   // col group
    const int ty = tid >> 4;   // row group

    const int row0 = blockIdx.y * 128;
    const int col0 = blockIdx.x * 128;

    // A-tile loader: one float4 per thread along K, stored transposed
    const int a_row = tid >> 1;          // 0..127
    const int a_k4  = (tid & 1) * 4;     // 0 or 4

    // B-tile loader (NN): one float4 per thread along N
    const int b_k  = tid >> 5;           // 0..7
    const int b_n4 = (tid & 31) * 4;     // 0..124

    float acc[8][8];
#pragma unroll
    for (int i = 0; i < 8; ++i)
#pragma unroll
        for (int j = 0; j < 8; ++j) acc[i][j] = 0.f;

    for (int k0 = 0; k0 < K; k0 += 8) {
        // Load A tile (transposed into As[k][m])
        float4 av = *(const float4*)(A + (size_t)(row0 + a_row) * K + k0 + a_k4);
        As[a_k4 + 0][a_row] = av.x;
        As[a_k4 + 1][a_row] = av.y;
        As[a_k4 + 2][a_row] = av.z;
        As[a_k4 + 3][a_row] = av.w;

        if (TRANSB) {
            // B[N,K]: Bs[k][n] = B[col0+n][k0+k]
            float4 bv = *(const float4*)(B + (size_t)(col0 + a_row) * K + k0 + a_k4);
            Bs[a_k4 + 0][a_row] = bv.x;
            Bs[a_k4 + 1][a_row] = bv.y;
            Bs[a_k4 + 2][a_row] = bv.z;
            Bs[a_k4 + 3][a_row] = bv.w;
        } else {
            // B[K,N]: direct
            float4 bv = *(const float4*)(B + (size_t)(k0 + b_k) * N + col0 + b_n4);
            *(float4*)&Bs[b_k][b_n4] = bv;
        }
        __syncthreads();

#pragma unroll
        for (int k = 0; k < 8; ++k) {
            float4 a0 = *(const float4*)&As[k][ty * 8];
            float4 a1 = *(const float4*)&As[k][ty * 8 + 4];
            float4 b0 = *(const float4*)&Bs[k][tx * 8];
            float4 b1 = *(const float4*)&Bs[k][tx * 8 + 4];
            float a[8] = {a0.x, a0.y, a0.z, a0.w, a1.x, a1.y, a1.z, a1.w};
            float b[8] = {b0.x, b0.y, b0.z, b0.w, b1.x, b1.y, b1.z, b1.w};
#pragma unroll
            for (int i = 0; i < 8; ++i)
#pragma unroll
                for (int j = 0; j < 8; ++j)
                    acc[i][j] = fmaf(a[i], b[j], acc[i][j]);
        }
        __syncthreads();
    }

#pragma unroll
    for (int i = 0; i < 8; ++i) {
        float* crow = C + (size_t)(row0 + ty * 8 + i) * N + col0 + tx * 8;
        float4 v0 = {acc[i][0] * alpha, acc[i][1] * alpha, acc[i][2] * alpha, acc[i][3] * alpha};
        float4 v1 = {acc[i][4] * alpha, acc[i][5] * alpha, acc[i][6] * alpha, acc[i][7] * alpha};
        *(float4*)(crow)     = v0;
        *(float4*)(crow + 4) = v1;
    }
}

// ---------------------------------------------------------------------------
// Causal softmax, in-place on g_S. One CTA per (batch, row).
// Masked entries (j > i) written as 0 so PV GEMM needs no mask.
// ---------------------------------------------------------------------------
__global__ __launch_bounds__(256) void softmax_causal(float* __restrict__ S)
{
    const int i = blockIdx.x;
    const int b = blockIdx.y;
    float* row = S + ((size_t)b * SLEN + i) * SLEN;

    __shared__ float sh[SLEN];
    __shared__ float red[256];
    const int tid = threadIdx.x;

    float mx = -1e30f;
    for (int j = tid; j < SLEN; j += 256) {
        float v = (j <= i) ? row[j] : -1e30f;
        sh[j] = v;
        mx = fmaxf(mx, v);
    }
    red[tid] = mx;
    __syncthreads();
    for (int s = 128; s > 0; s >>= 1) {
        if (tid < s) red[tid] = fmaxf(red[tid], red[tid + s]);
        __syncthreads();
    }
    mx = red[0];
    __syncthreads();

    float sum = 0.f;
    for (int j = tid; j < SLEN; j += 256) {
        float e = (j <= i) ? expf(sh[j] - mx) : 0.f;
        sh[j] = e;
        sum += e;
    }
    red[tid] = sum;
    __syncthreads();
    for (int s = 128; s > 0; s >>= 1) {
        if (tid < s) red[tid] += red[tid + s];
        __syncthreads();
    }
    const float inv = 1.f / red[0];
    __syncthreads();

    for (int j = tid; j < SLEN; j += 256)
        row[j] = sh[j] * inv;
}

// ---------------------------------------------------------------------------
extern "C" void kernel_launch(void* const* d_in, const int* in_sizes, int n_in,
                              void* d_out, int out_size)
{
    const float* X  = (const float*)d_in[0];
    const float* Wq = (const float*)d_in[1];
    const float* Wk = (const float*)d_in[2];
    const float* Wv = (const float*)d_in[3];
    float* out = (float*)d_out;

    float *Q, *K, *V, *Sc;
    cudaGetSymbolAddress((void**)&Q,  g_Q);
    cudaGetSymbolAddress((void**)&K,  g_K);
    cudaGetSymbolAddress((void**)&V,  g_V);
    cudaGetSymbolAddress((void**)&Sc, g_S);

    const int M = BATCH * SLEN;  // 8192
    dim3 blk(256);

    // QKV projections: [8192,1024] @ [1024,1024]
    dim3 g_qkv(DMODEL / 128, M / 128, 1);
    gemm128<0><<<g_qkv, blk>>>(X, Wq, Q, M, DMODEL, DMODEL, 0, 0, 0, 1.f);
    gemm128<0><<<g_qkv, blk>>>(X, Wk, K, M, DMODEL, DMODEL, 0, 0, 0, 1.f);
    gemm128<0><<<g_qkv, blk>>>(X, Wv, V, M, DMODEL, DMODEL, 0, 0, 0, 1.f);

    // Scores: per batch, [2048,2048] = Q @ K^T, scaled by 1/sqrt(1024)
    dim3 g_s(SLEN / 128, SLEN / 128, BATCH);
    gemm128<1><<<g_s, blk>>>(Q, K, Sc, SLEN, SLEN, DMODEL,
                             (size_t)SLEN * DMODEL, (size_t)SLEN * DMODEL,
                             (size_t)SLEN * SLEN, 1.f / 32.f);

    // Causal softmax in-place
    softmax_causal<<<dim3(SLEN, BATCH), 256>>>(Sc);

    // Output: per batch, [2048,1024] = P @ V
    dim3 g_o(DMODEL / 128, SLEN / 128, BATCH);
    gemm128<0><<<g_o, blk>>>(Sc, V, out, SLEN, DMODEL, SLEN,
                             (size_t)SLEN * SLEN, (size_t)SLEN * DMODEL,
                             (size_t)SLEN * DMODEL, 1.f);
}